// round 2
// baseline (speedup 1.0000x reference)
#include <cuda_runtime.h>

// PointConv: B=32, C=64, H=W=64, KH=KW=2 -> nH=nW=32, L=1024, n=256.
// out[b, p, l] = sum_k patch[b, k, l] * W[l, k, p] + bias[p, l]
//   k/p index = c*4 + kh*2 + kw ; l = ph*32 + pw
//   patch[b, k, l] = x[b, c, ph*2+kh, pw*2+kw]
//   out tensor    : out[b, c, ph*2+kh, pw*2+kw] = result[b, p]

#define BB 32
#define CC 64
#define HH 64
#define NN 256
#define LL 1024

__global__ void __launch_bounds__(256)
pointconv_kernel(const float* __restrict__ x,
                 const float* __restrict__ w,
                 const float* __restrict__ bias,
                 float* __restrict__ out)
{
    __shared__ float s_patch[NN * BB];   // [k][b] layout, 32 KB

    const int l  = blockIdx.x;
    const int ph = l >> 5;               // nW = 32
    const int pw = l & 31;
    const int tid = threadIdx.x;

    // ---- Phase 1: gather patch into smem ----
    // i in [0,4096): i = ((c*2)+kh)*32 + b  -> lanes vary b => conflict-free smem banks
    #pragma unroll
    for (int it = 0; it < 16; it++) {
        int i  = it * 256 + tid;
        int b  = i & 31;
        int kh = (i >> 5) & 1;
        int c  = i >> 6;
        const float2 v = *reinterpret_cast<const float2*>(
            x + (size_t)(((b * CC + c) * HH + (ph * 2 + kh)) * HH + pw * 2));
        int k = c * 4 + kh * 2;          // kw = 0
        s_patch[k * BB + b]       = v.x; // kw = 0
        s_patch[(k + 1) * BB + b] = v.y; // kw = 1
    }
    __syncthreads();

    const int tcol = tid & 31;           // 0..31 -> p tiles
    const int trow = tid >> 5;           // 0..7  -> b tile
    const int b0 = trow * 4;
    const int pA = tcol * 4;             // p in [0,128)
    const int pB = 128 + tcol * 4;       // p in [128,256)

    const float* __restrict__ wl = w + (size_t)l * (NN * NN);

    float acc[4][8];
    #pragma unroll
    for (int i = 0; i < 4; i++)
        #pragma unroll
        for (int j = 0; j < 8; j++) acc[i][j] = 0.0f;

    // ---- Phase 2: mainloop over k ----
    #pragma unroll 8
    for (int k = 0; k < NN; k++) {
        const float4 wa = *reinterpret_cast<const float4*>(wl + k * NN + pA);
        const float4 wb = *reinterpret_cast<const float4*>(wl + k * NN + pB);
        const float4 pv = *reinterpret_cast<const float4*>(&s_patch[k * BB + b0]);
        const float pvs[4] = {pv.x, pv.y, pv.z, pv.w};
        #pragma unroll
        for (int bi = 0; bi < 4; bi++) {
            const float pb = pvs[bi];
            acc[bi][0] += pb * wa.x;
            acc[bi][1] += pb * wa.y;
            acc[bi][2] += pb * wa.z;
            acc[bi][3] += pb * wa.w;
            acc[bi][4] += pb * wb.x;
            acc[bi][5] += pb * wb.y;
            acc[bi][6] += pb * wb.z;
            acc[bi][7] += pb * wb.w;
        }
    }

    // ---- bias (bias layout: [n, L]) ----
    float bA[4], bB[4];
    #pragma unroll
    for (int j = 0; j < 4; j++) {
        bA[j] = bias[(pA + j) * LL + l];
        bB[j] = bias[(pB + j) * LL + l];
    }

    // ---- Phase 3: scatter to out ----
    // pA group: c = tcol,      p offsets 0,1 -> kh=0 kw=0/1 ; 2,3 -> kh=1
    // pB group: c = 32 + tcol
    #pragma unroll
    for (int bi = 0; bi < 4; bi++) {
        const int b = b0 + bi;
        {
            float* o = out + (size_t)(((b * CC + tcol) * HH + ph * 2) * HH + pw * 2);
            *reinterpret_cast<float2*>(o) =
                make_float2(acc[bi][0] + bA[0], acc[bi][1] + bA[1]);
            *reinterpret_cast<float2*>(o + HH) =
                make_float2(acc[bi][2] + bA[2], acc[bi][3] + bA[3]);
        }
        {
            float* o = out + (size_t)(((b * CC + (32 + tcol)) * HH + ph * 2) * HH + pw * 2);
            *reinterpret_cast<float2*>(o) =
                make_float2(acc[bi][4] + bB[0], acc[bi][5] + bB[1]);
            *reinterpret_cast<float2*>(o + HH) =
                make_float2(acc[bi][6] + bB[2], acc[bi][7] + bB[3]);
        }
    }
}

extern "C" void kernel_launch(void* const* d_in, const int* in_sizes, int n_in,
                              void* d_out, int out_size)
{
    const float* x    = (const float*)d_in[0];
    const float* w    = (const float*)d_in[1];
    const float* bias = (const float*)d_in[2];
    float* out        = (float*)d_out;
    pointconv_kernel<<<LL, 256>>>(x, w, bias, out);
}

// round 3
// speedup vs baseline: 1.0048x; 1.0048x over previous
#include <cuda_runtime.h>

// PointConv: B=32, C=64, H=W=64, KH=KW=2 -> nH=nW=32, L=1024, n=256.
// out[b, p, l] = sum_k patch[b, k, l] * W[l, k, p] + bias[p, l]
//   k/p index = c*4 + kh*2 + kw ; l = ph*32 + pw
//   patch[b, k, l] = x[b, c, ph*2+kh, pw*2+kw]
//   out tensor    : out[b, c, ph*2+kh, pw*2+kw] = result[b, p]

#define BB 32
#define CC 64
#define HH 64
#define NN 256
#define LL 1024

__global__ void __launch_bounds__(256)
pointconv_kernel(const float* __restrict__ x,
                 const float* __restrict__ w,
                 const float* __restrict__ bias,
                 float* __restrict__ out)
{
    __shared__ float s_patch[NN * BB];   // [k][b] layout, 32 KB

    const int l  = blockIdx.x;
    const int ph = l >> 5;               // nW = 32
    const int pw = l & 31;
    const int tid = threadIdx.x;

    // ---- Phase 1: gather patch into smem ----
    // i in [0,4096): i = ((c*2)+kh)*32 + b  -> lanes vary b => conflict-free smem banks
    #pragma unroll
    for (int it = 0; it < 16; it++) {
        int i  = it * 256 + tid;
        int b  = i & 31;
        int kh = (i >> 5) & 1;
        int c  = i >> 6;
        const float2 v = *reinterpret_cast<const float2*>(
            x + (size_t)(((b * CC + c) * HH + (ph * 2 + kh)) * HH + pw * 2));
        int k = c * 4 + kh * 2;          // kw = 0
        s_patch[k * BB + b]       = v.x; // kw = 0
        s_patch[(k + 1) * BB + b] = v.y; // kw = 1
    }
    __syncthreads();

    const int tcol = tid & 31;           // 0..31 -> p tiles
    const int trow = tid >> 5;           // 0..7  -> b tile
    const int b0 = trow * 4;
    const int pA = tcol * 4;             // p in [0,128)
    const int pB = 128 + tcol * 4;       // p in [128,256)

    const float* __restrict__ wl = w + (size_t)l * (NN * NN);

    float acc[4][8];
    #pragma unroll
    for (int i = 0; i < 4; i++)
        #pragma unroll
        for (int j = 0; j < 8; j++) acc[i][j] = 0.0f;

    // ---- Phase 2: mainloop over k ----
    #pragma unroll 8
    for (int k = 0; k < NN; k++) {
        const float4 wa = *reinterpret_cast<const float4*>(wl + k * NN + pA);
        const float4 wb = *reinterpret_cast<const float4*>(wl + k * NN + pB);
        const float4 pv = *reinterpret_cast<const float4*>(&s_patch[k * BB + b0]);
        const float pvs[4] = {pv.x, pv.y, pv.z, pv.w};
        #pragma unroll
        for (int bi = 0; bi < 4; bi++) {
            const float pb = pvs[bi];
            acc[bi][0] += pb * wa.x;
            acc[bi][1] += pb * wa.y;
            acc[bi][2] += pb * wa.z;
            acc[bi][3] += pb * wa.w;
            acc[bi][4] += pb * wb.x;
            acc[bi][5] += pb * wb.y;
            acc[bi][6] += pb * wb.z;
            acc[bi][7] += pb * wb.w;
        }
    }

    // ---- bias (bias layout: [n, L]) ----
    float bA[4], bB[4];
    #pragma unroll
    for (int j = 0; j < 4; j++) {
        bA[j] = bias[(pA + j) * LL + l];
        bB[j] = bias[(pB + j) * LL + l];
    }

    // ---- Phase 3: scatter to out ----
    // pA group: c = tcol,      p offsets 0,1 -> kh=0 kw=0/1 ; 2,3 -> kh=1
    // pB group: c = 32 + tcol
    #pragma unroll
    for (int bi = 0; bi < 4; bi++) {
        const int b = b0 + bi;
        {
            float* o = out + (size_t)(((b * CC + tcol) * HH + ph * 2) * HH + pw * 2);
            *reinterpret_cast<float2*>(o) =
                make_float2(acc[bi][0] + bA[0], acc[bi][1] + bA[1]);
            *reinterpret_cast<float2*>(o + HH) =
                make_float2(acc[bi][2] + bA[2], acc[bi][3] + bA[3]);
        }
        {
            float* o = out + (size_t)(((b * CC + (32 + tcol)) * HH + ph * 2) * HH + pw * 2);
            *reinterpret_cast<float2*>(o) =
                make_float2(acc[bi][4] + bB[0], acc[bi][5] + bB[1]);
            *reinterpret_cast<float2*>(o + HH) =
                make_float2(acc[bi][6] + bB[2], acc[bi][7] + bB[3]);
        }
    }
}

extern "C" void kernel_launch(void* const* d_in, const int* in_sizes, int n_in,
                              void* d_out, int out_size)
{
    const float* x    = (const float*)d_in[0];
    const float* w    = (const float*)d_in[1];
    const float* bias = (const float*)d_in[2];
    float* out        = (float*)d_out;
    pointconv_kernel<<<LL, 256>>>(x, w, bias, out);
}

// round 4
// speedup vs baseline: 1.6022x; 1.5946x over previous
#include <cuda_runtime.h>
#include <cstdint>

// PointConv: B=32, C=64, H=W=64, KH=KW=2 -> nH=nW=32, L=1024, n=256.
// out[b, p, l] = sum_k patch[b, k, l] * W[l, k, p] + bias[p, l]

#define BB 32
#define CC 64
#define HH 64
#define NN 256
#define LL 1024

#define KS    8                 // k-rows per pipeline stage
#define PIPE  4                 // stages in flight
#define NSTG  (NN / KS)         // 32 stages
#define SMEM_FLOATS (NN * BB + PIPE * KS * NN)   // 8192 + 8192
#define SMEM_BYTES  (SMEM_FLOATS * 4)            // 64 KB

typedef unsigned long long u64;

__device__ __forceinline__ void cp_async16(uint32_t saddr, const void* gptr) {
    asm volatile("cp.async.ca.shared.global [%0], [%1], 16;\n"
                 :: "r"(saddr), "l"(gptr));
}
__device__ __forceinline__ void cp_commit() {
    asm volatile("cp.async.commit_group;\n" ::: "memory");
}
template <int N>
__device__ __forceinline__ void cp_wait() {
    asm volatile("cp.async.wait_group %0;\n" :: "n"(N) : "memory");
}
__device__ __forceinline__ u64 pack2(float a, float b) {
    u64 r;
    asm("mov.b64 %0, {%1, %2};" : "=l"(r) : "f"(a), "f"(b));
    return r;
}
__device__ __forceinline__ void fma2(u64& acc, u64 a, u64 b) {
    asm("fma.rn.f32x2 %0, %1, %2, %0;" : "+l"(acc) : "l"(a), "l"(b));
}
__device__ __forceinline__ void unpack2(u64 v, float& lo, float& hi) {
    asm("mov.b64 {%0, %1}, %2;" : "=f"(lo), "=f"(hi) : "l"(v));
}

__global__ void __launch_bounds__(256)
pointconv_kernel(const float* __restrict__ x,
                 const float* __restrict__ w,
                 const float* __restrict__ bias,
                 float* __restrict__ out)
{
    extern __shared__ float smem[];
    float* s_patch = smem;                 // [k][b], 32 KB
    float* s_w     = smem + NN * BB;       // [PIPE][KS][NN], 32 KB

    const int l   = blockIdx.x;
    const int ph  = l >> 5;
    const int pw  = l & 31;
    const int tid = threadIdx.x;

    const float* __restrict__ wl = w + (size_t)l * (NN * NN);

    // ---- kick off weight prefetch for the first PIPE stages (overlaps patch gather) ----
    const uint32_t sw_base = (uint32_t)__cvta_generic_to_shared(s_w);
    #pragma unroll
    for (int s = 0; s < PIPE; s++) {
        const float* src = wl + s * (KS * NN);
        uint32_t dst = sw_base + (uint32_t)(s * (KS * NN) * 4);
        #pragma unroll
        for (int c = 0; c < (KS * NN) / (256 * 4); c++) {    // 2 chunks of 16B per thread
            int chunk = c * 256 + tid;
            cp_async16(dst + chunk * 16, src + chunk * 4);
        }
        cp_commit();
    }

    // ---- Phase 1: gather patch into smem [k][b] ----
    #pragma unroll
    for (int it = 0; it < 16; it++) {
        int i  = it * 256 + tid;
        int b  = i & 31;
        int kh = (i >> 5) & 1;
        int c  = i >> 6;
        const float2 v = *reinterpret_cast<const float2*>(
            x + (size_t)(((b * CC + c) * HH + (ph * 2 + kh)) * HH + pw * 2));
        int k = c * 4 + kh * 2;
        s_patch[k * BB + b]       = v.x;   // kw = 0
        s_patch[(k + 1) * BB + b] = v.y;   // kw = 1
    }

    const int tcol = tid & 31;
    const int trow = tid >> 5;
    const int b0 = trow * 4;
    const int pA = tcol * 4;
    const int pB = 128 + tcol * 4;

    // acc pairs: [bi][0]=(pA,pA+1) [1]=(pA+2,pA+3) [2]=(pB,pB+1) [3]=(pB+2,pB+3)
    u64 acc[4][4];
    #pragma unroll
    for (int i = 0; i < 4; i++)
        #pragma unroll
        for (int j = 0; j < 4; j++) acc[i][j] = 0ULL;

    // ---- Phase 2: pipelined mainloop ----
    #pragma unroll 1
    for (int s = 0; s < NSTG; s++) {
        cp_wait<PIPE - 1>();
        __syncthreads();

        const float* wbuf = s_w + (s & (PIPE - 1)) * (KS * NN);
        #pragma unroll
        for (int kk = 0; kk < KS; kk++) {
            const int k = s * KS + kk;
            const ulonglong2 wa = *reinterpret_cast<const ulonglong2*>(wbuf + kk * NN + pA);
            const ulonglong2 wb = *reinterpret_cast<const ulonglong2*>(wbuf + kk * NN + pB);
            const float4 pv = *reinterpret_cast<const float4*>(&s_patch[k * BB + b0]);
            u64 pp[4];
            pp[0] = pack2(pv.x, pv.x);
            pp[1] = pack2(pv.y, pv.y);
            pp[2] = pack2(pv.z, pv.z);
            pp[3] = pack2(pv.w, pv.w);
            #pragma unroll
            for (int bi = 0; bi < 4; bi++) {
                fma2(acc[bi][0], pp[bi], wa.x);
                fma2(acc[bi][1], pp[bi], wa.y);
                fma2(acc[bi][2], pp[bi], wb.x);
                fma2(acc[bi][3], pp[bi], wb.y);
            }
        }
        __syncthreads();   // all warps done with buf[s & 3] before it is refilled

        const int ns = s + PIPE;
        if (ns < NSTG) {
            const float* src = wl + ns * (KS * NN);
            uint32_t dst = sw_base + (uint32_t)((ns & (PIPE - 1)) * (KS * NN) * 4);
            #pragma unroll
            for (int c = 0; c < (KS * NN) / (256 * 4); c++) {
                int chunk = c * 256 + tid;
                cp_async16(dst + chunk * 16, src + chunk * 4);
            }
        }
        cp_commit();       // commit every iteration (possibly empty) to keep group counting aligned
    }

    // ---- bias (layout [n, L]; zeros in practice but honored) ----
    float bA[4], bB[4];
    #pragma unroll
    for (int j = 0; j < 4; j++) {
        bA[j] = bias[(pA + j) * LL + l];
        bB[j] = bias[(pB + j) * LL + l];
    }

    // ---- Phase 3: scatter to out ----
    #pragma unroll
    for (int bi = 0; bi < 4; bi++) {
        const int b = b0 + bi;
        float a0, a1, a2, a3;
        unpack2(acc[bi][0], a0, a1);
        unpack2(acc[bi][1], a2, a3);
        {
            float* o = out + (size_t)(((b * CC + tcol) * HH + ph * 2) * HH + pw * 2);
            *reinterpret_cast<float2*>(o)      = make_float2(a0 + bA[0], a1 + bA[1]);
            *reinterpret_cast<float2*>(o + HH) = make_float2(a2 + bA[2], a3 + bA[3]);
        }
        unpack2(acc[bi][2], a0, a1);
        unpack2(acc[bi][3], a2, a3);
        {
            float* o = out + (size_t)(((b * CC + (32 + tcol)) * HH + ph * 2) * HH + pw * 2);
            *reinterpret_cast<float2*>(o)      = make_float2(a0 + bB[0], a1 + bB[1]);
            *reinterpret_cast<float2*>(o + HH) = make_float2(a2 + bB[2], a3 + bB[3]);
        }
    }
}

extern "C" void kernel_launch(void* const* d_in, const int* in_sizes, int n_in,
                              void* d_out, int out_size)
{
    const float* x    = (const float*)d_in[0];
    const float* w    = (const float*)d_in[1];
    const float* bias = (const float*)d_in[2];
    float* out        = (float*)d_out;

    cudaFuncSetAttribute(pointconv_kernel,
                         cudaFuncAttributeMaxDynamicSharedMemorySize, SMEM_BYTES);
    pointconv_kernel<<<LL, 256, SMEM_BYTES>>>(x, w, bias, out);
}

// round 5
// speedup vs baseline: 1.6535x; 1.0320x over previous
#include <cuda_runtime.h>
#include <cstdint>

// PointConv: B=32, C=64, H=W=64, KH=KW=2 -> nH=nW=32, L=1024, n=256.
// out[b, p, l] = sum_k patch[b, k, l] * W[l, k, p] + bias[p, l]

#define BB 32
#define CC 64
#define HH 64
#define NN 256
#define LL 1024

#define KS    8                 // k-rows per pipeline stage (8 KB per bulk copy)
#define PIPE  4                 // stages in flight
#define NSTG  (NN / KS)         // 32 stages
#define STAGE_FLOATS (KS * NN)  // 2048
#define STAGE_BYTES  (STAGE_FLOATS * 4)  // 8192
#define SMEM_FLOATS (NN * BB + PIPE * STAGE_FLOATS)  // 8192 + 8192
#define SMEM_BYTES  (SMEM_FLOATS * 4)                // 64 KB

typedef unsigned long long u64;

__device__ __forceinline__ u64 pack2(float a, float b) {
    u64 r;
    asm("mov.b64 %0, {%1, %2};" : "=l"(r) : "f"(a), "f"(b));
    return r;
}
__device__ __forceinline__ void fma2(u64& acc, u64 a, u64 b) {
    asm("fma.rn.f32x2 %0, %1, %2, %0;" : "+l"(acc) : "l"(a), "l"(b));
}
__device__ __forceinline__ void unpack2(u64 v, float& lo, float& hi) {
    asm("mov.b64 {%0, %1}, %2;" : "=f"(lo), "=f"(hi) : "l"(v));
}
__device__ __forceinline__ void mbar_init(uint32_t mbar, uint32_t count) {
    asm volatile("mbarrier.init.shared::cta.b64 [%0], %1;" :: "r"(mbar), "r"(count) : "memory");
}
__device__ __forceinline__ void mbar_expect_tx(uint32_t mbar, uint32_t bytes) {
    asm volatile("mbarrier.arrive.expect_tx.shared::cta.b64 _, [%0], %1;"
                 :: "r"(mbar), "r"(bytes) : "memory");
}
__device__ __forceinline__ void bulk_g2s(uint32_t dst, const void* src, uint32_t bytes, uint32_t mbar) {
    asm volatile("cp.async.bulk.shared::cta.global.mbarrier::complete_tx::bytes [%0], [%1], %2, [%3];"
                 :: "r"(dst), "l"(src), "r"(bytes), "r"(mbar) : "memory");
}
__device__ __forceinline__ void mbar_wait(uint32_t mbar, uint32_t parity) {
    asm volatile(
        "{\n\t"
        ".reg .pred P1;\n\t"
        "WAIT_LOOP_%=:\n\t"
        "mbarrier.try_wait.parity.shared::cta.b64 P1, [%0], %1, 0x989680;\n\t"
        "@P1 bra.uni WAIT_DONE_%=;\n\t"
        "bra.uni WAIT_LOOP_%=;\n\t"
        "WAIT_DONE_%=:\n\t"
        "}"
        :: "r"(mbar), "r"(parity) : "memory");
}

__global__ void __launch_bounds__(256)
pointconv_kernel(const float* __restrict__ x,
                 const float* __restrict__ w,
                 const float* __restrict__ bias,
                 float* __restrict__ out)
{
    extern __shared__ float smem[];
    float* s_patch = smem;                 // [k][b], 32 KB
    float* s_w     = smem + NN * BB;       // [PIPE][KS][NN], 32 KB
    __shared__ __align__(8) u64 s_mbar[PIPE];

    const int l   = blockIdx.x;
    const int ph  = l >> 5;
    const int pw  = l & 31;
    const int tid = threadIdx.x;

    const float* __restrict__ wl = w + (size_t)l * (NN * NN);
    const uint32_t sw_base   = (uint32_t)__cvta_generic_to_shared(s_w);
    const uint32_t mbar_base = (uint32_t)__cvta_generic_to_shared(&s_mbar[0]);

    // ---- init mbarriers, then issue bulk prefetch for the first PIPE stages ----
    if (tid == 0) {
        #pragma unroll
        for (int s = 0; s < PIPE; s++) mbar_init(mbar_base + s * 8, 1);
        // make the initialized barriers visible to the async proxy before TMA uses them
        asm volatile("fence.proxy.async.shared::cta;" ::: "memory");
        #pragma unroll
        for (int s = 0; s < PIPE; s++) {
            uint32_t mb = mbar_base + s * 8;
            mbar_expect_tx(mb, STAGE_BYTES);
            bulk_g2s(sw_base + s * STAGE_BYTES, wl + s * STAGE_FLOATS, STAGE_BYTES, mb);
        }
    }

    // ---- Phase 1: gather patch into smem [k][b] (overlaps the bulk copies) ----
    #pragma unroll
    for (int it = 0; it < 16; it++) {
        int i  = it * 256 + tid;
        int b  = i & 31;
        int kh = (i >> 5) & 1;
        int c  = i >> 6;
        const float2 v = *reinterpret_cast<const float2*>(
            x + (size_t)(((b * CC + c) * HH + (ph * 2 + kh)) * HH + pw * 2));
        int k = c * 4 + kh * 2;
        s_patch[k * BB + b]       = v.x;   // kw = 0
        s_patch[(k + 1) * BB + b] = v.y;   // kw = 1
    }
    __syncthreads();                        // patch visible + mbarriers initialized for all

    const int tcol = tid & 31;
    const int trow = tid >> 5;
    const int b0 = trow * 4;
    const int pA = tcol * 4;
    const int pB = 128 + tcol * 4;

    u64 acc[4][4];
    #pragma unroll
    for (int i = 0; i < 4; i++)
        #pragma unroll
        for (int j = 0; j < 4; j++) acc[i][j] = 0ULL;

    // ---- Phase 2: TMA-fed pipelined mainloop ----
    #pragma unroll 1
    for (int s = 0; s < NSTG; s++) {
        const int      buf    = s & (PIPE - 1);
        const uint32_t parity = (s >> 2) & 1;
        mbar_wait(mbar_base + buf * 8, parity);

        const float* wbuf = s_w + buf * STAGE_FLOATS;
        #pragma unroll
        for (int kk = 0; kk < KS; kk++) {
            const int k = s * KS + kk;
            const ulonglong2 wa = *reinterpret_cast<const ulonglong2*>(wbuf + kk * NN + pA);
            const ulonglong2 wb = *reinterpret_cast<const ulonglong2*>(wbuf + kk * NN + pB);
            const float4 pv = *reinterpret_cast<const float4*>(&s_patch[k * BB + b0]);
            u64 pp[4];
            pp[0] = pack2(pv.x, pv.x);
            pp[1] = pack2(pv.y, pv.y);
            pp[2] = pack2(pv.z, pv.z);
            pp[3] = pack2(pv.w, pv.w);
            #pragma unroll
            for (int bi = 0; bi < 4; bi++) {
                fma2(acc[bi][0], pp[bi], wa.x);
                fma2(acc[bi][1], pp[bi], wa.y);
                fma2(acc[bi][2], pp[bi], wb.x);
                fma2(acc[bi][3], pp[bi], wb.y);
            }
        }

        const int ns = s + PIPE;
        if (ns < NSTG) {
            __syncthreads();               // all warps done reading buf before refill
            if (tid == 0) {
                uint32_t mb = mbar_base + buf * 8;
                mbar_expect_tx(mb, STAGE_BYTES);
                bulk_g2s(sw_base + buf * STAGE_BYTES, wl + ns * STAGE_FLOATS, STAGE_BYTES, mb);
            }
        }
    }

    // ---- bias (layout [n, L]) ----
    float bA[4], bB[4];
    #pragma unroll
    for (int j = 0; j < 4; j++) {
        bA[j] = bias[(pA + j) * LL + l];
        bB[j] = bias[(pB + j) * LL + l];
    }

    // ---- Phase 3: scatter to out ----
    #pragma unroll
    for (int bi = 0; bi < 4; bi++) {
        const int b = b0 + bi;
        float a0, a1, a2, a3;
        unpack2(acc[bi][0], a0, a1);
        unpack2(acc[bi][1], a2, a3);
        {
            float* o = out + (size_t)(((b * CC + tcol) * HH + ph * 2) * HH + pw * 2);
            *reinterpret_cast<float2*>(o)      = make_float2(a0 + bA[0], a1 + bA[1]);
            *reinterpret_cast<float2*>(o + HH) = make_float2(a2 + bA[2], a3 + bA[3]);
        }
        unpack2(acc[bi][2], a0, a1);
        unpack2(acc[bi][3], a2, a3);
        {
            float* o = out + (size_t)(((b * CC + (32 + tcol)) * HH + ph * 2) * HH + pw * 2);
            *reinterpret_cast<float2*>(o)      = make_float2(a0 + bB[0], a1 + bB[1]);
            *reinterpret_cast<float2*>(o + HH) = make_float2(a2 + bB[2], a3 + bB[3]);
        }
    }
}

extern "C" void kernel_launch(void* const* d_in, const int* in_sizes, int n_in,
                              void* d_out, int out_size)
{
    const float* x    = (const float*)d_in[0];
    const float* w    = (const float*)d_in[1];
    const float* bias = (const float*)d_in[2];
    float* out        = (float*)d_out;

    cudaFuncSetAttribute(pointconv_kernel,
                         cudaFuncAttributeMaxDynamicSharedMemorySize, SMEM_BYTES);
    pointconv_kernel<<<LL, 256, SMEM_BYTES>>>(x, w, bias, out);
}

// round 6
// speedup vs baseline: 1.6793x; 1.0156x over previous
#include <cuda_runtime.h>
#include <cstdint>

// PointConv: B=32, C=64, H=W=64, KH=KW=2 -> nH=nW=32, L=1024, n=256.
// out[b, p, l] = sum_k patch[b, k, l] * W[l, k, p] + bias[p, l]
// Tile: thread owns 16 b (as 8 f32x2 pairs) x 2 p. Warps partition p.

#define BB 32
#define CC 64
#define HH 64
#define NN 256
#define LL 1024

#define KS    8                 // k-rows per pipeline stage (8 KB per bulk copy)
#define PIPE  4                 // stages in flight
#define NSTG  (NN / KS)         // 32 stages
#define STAGE_FLOATS (KS * NN)  // 2048
#define STAGE_BYTES  (STAGE_FLOATS * 4)  // 8192
#define SMEM_FLOATS (NN * BB + PIPE * STAGE_FLOATS)  // 8192 + 8192
#define SMEM_BYTES  (SMEM_FLOATS * 4)                // 64 KB

typedef unsigned long long u64;

__device__ __forceinline__ u64 pack2(float a, float b) {
    u64 r;
    asm("mov.b64 %0, {%1, %2};" : "=l"(r) : "f"(a), "f"(b));
    return r;
}
__device__ __forceinline__ void fma2(u64& acc, u64 a, u64 b) {
    asm("fma.rn.f32x2 %0, %1, %2, %0;" : "+l"(acc) : "l"(a), "l"(b));
}
__device__ __forceinline__ void unpack2(u64 v, float& lo, float& hi) {
    asm("mov.b64 {%0, %1}, %2;" : "=f"(lo), "=f"(hi) : "l"(v));
}
__device__ __forceinline__ void mbar_init(uint32_t mbar, uint32_t count) {
    asm volatile("mbarrier.init.shared::cta.b64 [%0], %1;" :: "r"(mbar), "r"(count) : "memory");
}
__device__ __forceinline__ void mbar_expect_tx(uint32_t mbar, uint32_t bytes) {
    asm volatile("mbarrier.arrive.expect_tx.shared::cta.b64 _, [%0], %1;"
                 :: "r"(mbar), "r"(bytes) : "memory");
}
__device__ __forceinline__ void bulk_g2s(uint32_t dst, const void* src, uint32_t bytes, uint32_t mbar) {
    asm volatile("cp.async.bulk.shared::cta.global.mbarrier::complete_tx::bytes [%0], [%1], %2, [%3];"
                 :: "r"(dst), "l"(src), "r"(bytes), "r"(mbar) : "memory");
}
__device__ __forceinline__ void mbar_wait(uint32_t mbar, uint32_t parity) {
    asm volatile(
        "{\n\t"
        ".reg .pred P1;\n\t"
        "WAIT_LOOP_%=:\n\t"
        "mbarrier.try_wait.parity.shared::cta.b64 P1, [%0], %1, 0x989680;\n\t"
        "@P1 bra.uni WAIT_DONE_%=;\n\t"
        "bra.uni WAIT_LOOP_%=;\n\t"
        "WAIT_DONE_%=:\n\t"
        "}"
        :: "r"(mbar), "r"(parity) : "memory");
}

__global__ void __launch_bounds__(256, 3)
pointconv_kernel(const float* __restrict__ x,
                 const float* __restrict__ w,
                 const float* __restrict__ bias,
                 float* __restrict__ out)
{
    extern __shared__ float smem[];
    float* s_patch = smem;                 // [k][b], 32 KB
    float* s_w     = smem + NN * BB;       // [PIPE][KS][NN], 32 KB
    __shared__ __align__(8) u64 s_mbar[PIPE];

    const int l   = blockIdx.x;
    const int ph  = l >> 5;
    const int pw  = l & 31;
    const int tid = threadIdx.x;

    const float* __restrict__ wl = w + (size_t)l * (NN * NN);
    const uint32_t sw_base   = (uint32_t)__cvta_generic_to_shared(s_w);
    const uint32_t mbar_base = (uint32_t)__cvta_generic_to_shared(&s_mbar[0]);

    // ---- init mbarriers, then issue bulk prefetch for the first PIPE stages ----
    if (tid == 0) {
        #pragma unroll
        for (int s = 0; s < PIPE; s++) mbar_init(mbar_base + s * 8, 1);
        asm volatile("fence.proxy.async.shared::cta;" ::: "memory");
        #pragma unroll
        for (int s = 0; s < PIPE; s++) {
            uint32_t mb = mbar_base + s * 8;
            mbar_expect_tx(mb, STAGE_BYTES);
            bulk_g2s(sw_base + s * STAGE_BYTES, wl + s * STAGE_FLOATS, STAGE_BYTES, mb);
        }
    }

    // ---- Phase 1: gather patch into smem [k][b] (overlaps the bulk copies) ----
    #pragma unroll
    for (int it = 0; it < 16; it++) {
        int i  = it * 256 + tid;
        int b  = i & 31;
        int kh = (i >> 5) & 1;
        int c  = i >> 6;
        const float2 v = *reinterpret_cast<const float2*>(
            x + (size_t)(((b * CC + c) * HH + (ph * 2 + kh)) * HH + pw * 2));
        int k = c * 4 + kh * 2;
        s_patch[k * BB + b]       = v.x;   // kw = 0
        s_patch[(k + 1) * BB + b] = v.y;   // kw = 1
    }
    __syncthreads();                        // patch visible + mbarriers initialized

    // ---- new tile mapping: 16 b (8 pairs) x 2 p per thread ----
    const int pcol = tid & 127;            // p-pair index
    const int p0   = pcol * 2;             // p0 even, pair (p0, p0+1)
    const int b0   = (tid >> 7) * 16;      // 0 or 16

    u64 acc[8][2];                          // [b-pair][p within pair]
    #pragma unroll
    for (int i = 0; i < 8; i++) { acc[i][0] = 0ULL; acc[i][1] = 0ULL; }

    // ---- Phase 2: TMA-fed pipelined mainloop ----
    #pragma unroll 1
    for (int s = 0; s < NSTG; s++) {
        const int      buf    = s & (PIPE - 1);
        const uint32_t parity = (s >> 2) & 1;
        mbar_wait(mbar_base + buf * 8, parity);

        const float* wbuf = s_w + buf * STAGE_FLOATS;
        #pragma unroll
        for (int kk = 0; kk < KS; kk++) {
            const int k = s * KS + kk;
            // patch: 16 b values = 4 broadcast LDS.128, each = 2 (b,b+1) f32x2 pairs
            const ulonglong2 q0 = *reinterpret_cast<const ulonglong2*>(&s_patch[k * BB + b0]);
            const ulonglong2 q1 = *reinterpret_cast<const ulonglong2*>(&s_patch[k * BB + b0 + 4]);
            const ulonglong2 q2 = *reinterpret_cast<const ulonglong2*>(&s_patch[k * BB + b0 + 8]);
            const ulonglong2 q3 = *reinterpret_cast<const ulonglong2*>(&s_patch[k * BB + b0 + 12]);
            // weight: 2 values for this thread's p pair
            const float2 wv = *reinterpret_cast<const float2*>(wbuf + kk * NN + p0);
            const u64 wd0 = pack2(wv.x, wv.x);
            const u64 wd1 = pack2(wv.y, wv.y);
            const u64 pb[8] = {q0.x, q0.y, q1.x, q1.y, q2.x, q2.y, q3.x, q3.y};
            #pragma unroll
            for (int j = 0; j < 8; j++) {
                fma2(acc[j][0], pb[j], wd0);
                fma2(acc[j][1], pb[j], wd1);
            }
        }

        const int ns = s + PIPE;
        if (ns < NSTG) {
            __syncthreads();               // all warps done reading buf before refill
            if (tid == 0) {
                uint32_t mb = mbar_base + buf * 8;
                mbar_expect_tx(mb, STAGE_BYTES);
                bulk_g2s(sw_base + buf * STAGE_BYTES, wl + ns * STAGE_FLOATS, STAGE_BYTES, mb);
            }
        }
    }

    // ---- bias (layout [n, L]) ----
    const float bias0 = bias[p0 * LL + l];
    const float bias1 = bias[(p0 + 1) * LL + l];

    // ---- Phase 3: scatter to out ----
    // p0 = c*4 + kh*2 (+kw); pair (p0, p0+1) -> kw = 0,1 adjacent in W -> float2 store
    const int c  = p0 >> 2;
    const int kh = (p0 >> 1) & 1;
    #pragma unroll
    for (int j = 0; j < 8; j++) {
        float a0, a1, c0, c1;
        unpack2(acc[j][0], a0, a1);        // (b, b+1) at p0
        unpack2(acc[j][1], c0, c1);        // (b, b+1) at p0+1
        const int b = b0 + j * 2;
        float* oA = out + (size_t)(((b * CC + c) * HH + (ph * 2 + kh)) * HH + pw * 2);
        float* oB = out + (size_t)((((b + 1) * CC + c) * HH + (ph * 2 + kh)) * HH + pw * 2);
        *reinterpret_cast<float2*>(oA) = make_float2(a0 + bias0, c0 + bias1);
        *reinterpret_cast<float2*>(oB) = make_float2(a1 + bias0, c1 + bias1);
    }
}

extern "C" void kernel_launch(void* const* d_in, const int* in_sizes, int n_in,
                              void* d_out, int out_size)
{
    const float* x    = (const float*)d_in[0];
    const float* w    = (const float*)d_in[1];
    const float* bias = (const float*)d_in[2];
    float* out        = (float*)d_out;

    cudaFuncSetAttribute(pointconv_kernel,
                         cudaFuncAttributeMaxDynamicSharedMemorySize, SMEM_BYTES);
    pointconv_kernel<<<LL, 256, SMEM_BYTES>>>(x, w, bias, out);
}

// round 8
// speedup vs baseline: 1.8640x; 1.1100x over previous
#include <cuda_runtime.h>
#include <cstdint>

// PointConv: B=32, C=64, H=W=64, KH=KW=2 -> L=1024, n=256.
// Per l: D[p, b] = sum_k W[l][k][p] * patch[b][k] + bias[p, l]
// fp32 via 3-term bf16 split on mma.sync.m16n8k16 (portable HMMA path).

#define HH 64
#define CC 64
#define NB 32
#define NN 256
#define LL 1024

#define KSTAGE 32
#define NSTG   8
#define W_STAGE_BYTES (KSTAGE * NN * 4)        // 32768

#define PADK  264                               // bf16 elems per row
#define ROWB  (PADK * 2)                        // 528 bytes (16B-aligned, 4-bank stagger)
#define ATILE (KSTAGE * ROWB)                   // 16896 bytes (one of hi/mid)

#define OFF_W0   0                              // 2 x 32768 = 65536
#define OFF_A    65536                          // 2 stage-bufs x (AH + AM) = 2*33792
#define OFF_PH   133120                         // patch hi: 32 x 528 = 16896
#define OFF_PM   150016                         // patch mid
#define OFF_CTRL 166912                         // mbarriers
#define SMEM_TOTAL 166976

typedef unsigned long long u64;

__device__ __forceinline__ uint32_t cvt2(float lo, float hi) {  // pack {lo=low16, hi=high16}
    uint32_t r;
    asm("cvt.rn.bf16x2.f32 %0, %1, %2;" : "=r"(r) : "f"(hi), "f"(lo));
    return r;
}
__device__ __forceinline__ float lo_f(uint32_t p) { return __uint_as_float(p << 16); }
__device__ __forceinline__ float hi_f(uint32_t p) { return __uint_as_float(p & 0xffff0000u); }

__device__ __forceinline__ void mbar_init(uint32_t mbar, uint32_t count) {
    asm volatile("mbarrier.init.shared::cta.b64 [%0], %1;" :: "r"(mbar), "r"(count) : "memory");
}
__device__ __forceinline__ void mbar_expect_tx(uint32_t mbar, uint32_t bytes) {
    asm volatile("mbarrier.arrive.expect_tx.shared::cta.b64 _, [%0], %1;"
                 :: "r"(mbar), "r"(bytes) : "memory");
}
__device__ __forceinline__ void bulk_g2s(uint32_t dst, const void* src, uint32_t bytes, uint32_t mbar) {
    asm volatile("cp.async.bulk.shared::cta.global.mbarrier::complete_tx::bytes [%0], [%1], %2, [%3];"
                 :: "r"(dst), "l"(src), "r"(bytes), "r"(mbar) : "memory");
}
__device__ __forceinline__ void mbar_wait(uint32_t mbar, uint32_t parity) {
    asm volatile(
        "{\n\t.reg .pred P1;\n\t"
        "WAIT_LOOP_%=:\n\t"
        "mbarrier.try_wait.parity.shared::cta.b64 P1, [%0], %1, 0x989680;\n\t"
        "@P1 bra.uni WAIT_DONE_%=;\n\t"
        "bra.uni WAIT_LOOP_%=;\n\t"
        "WAIT_DONE_%=:\n\t}"
        :: "r"(mbar), "r"(parity) : "memory");
}
__device__ __forceinline__ void ldsm4t(uint32_t& r0, uint32_t& r1, uint32_t& r2, uint32_t& r3,
                                       uint32_t addr) {
    asm volatile("ldmatrix.sync.aligned.m8n8.x4.trans.shared.b16 {%0,%1,%2,%3}, [%4];"
                 : "=r"(r0), "=r"(r1), "=r"(r2), "=r"(r3) : "r"(addr));
}
__device__ __forceinline__ void mma_bf16(float* d, const uint32_t* a, const uint32_t* b) {
    asm volatile(
        "mma.sync.aligned.m16n8k16.row.col.f32.bf16.bf16.f32 "
        "{%0,%1,%2,%3}, {%4,%5,%6,%7}, {%8,%9}, {%0,%1,%2,%3};"
        : "+f"(d[0]), "+f"(d[1]), "+f"(d[2]), "+f"(d[3])
        : "r"(a[0]), "r"(a[1]), "r"(a[2]), "r"(a[3]), "r"(b[0]), "r"(b[1]));
}

__global__ void __launch_bounds__(256)
pointconv_mma(const float* __restrict__ x,
              const float* __restrict__ w,
              const float* __restrict__ bias,
              float* __restrict__ out)
{
    extern __shared__ char smem[];
    const uint32_t sbase = (uint32_t)__cvta_generic_to_shared(smem);
    const int tid  = threadIdx.x;
    const int wid  = tid >> 5;
    const int lane = tid & 31;
    const int l  = blockIdx.x;
    const int ph = l >> 5, pw = l & 31;
    const float* __restrict__ wl = w + (size_t)l * (NN * NN);

    const uint32_t mb0 = sbase + OFF_CTRL;
    const uint32_t mb1 = sbase + OFF_CTRL + 8;

    // ---- mbarriers + prefetch first 2 W stages ----
    if (tid == 0) {
        mbar_init(mb0, 1);
        mbar_init(mb1, 1);
        asm volatile("fence.proxy.async.shared::cta;" ::: "memory");
        #pragma unroll
        for (int s = 0; s < 2; s++) {
            uint32_t mb = s ? mb1 : mb0;
            mbar_expect_tx(mb, W_STAGE_BYTES);
            bulk_g2s(sbase + OFF_W0 + s * W_STAGE_BYTES, wl + s * (KSTAGE * NN),
                     W_STAGE_BYTES, mb);
        }
    }

    // ---- patch gather + bf16 hi/mid split -> [b][k] (stride 528B) ----
    {
        const int b  = tid & 31;
        const int cg = tid >> 5;
        #pragma unroll
        for (int ci = 0; ci < 8; ci++) {
            const int c = cg * 8 + ci;
            #pragma unroll
            for (int kh = 0; kh < 2; kh++) {
                const float2 v = *reinterpret_cast<const float2*>(
                    x + (size_t)(((b * CC + c) * HH + 2 * ph + kh) * HH + 2 * pw));
                const int k = c * 4 + kh * 2;
                const uint32_t hp = cvt2(v.x, v.y);
                const uint32_t mp = cvt2(v.x - lo_f(hp), v.y - hi_f(hp));
                *reinterpret_cast<uint32_t*>(smem + OFF_PH + b * ROWB + k * 2) = hp;
                *reinterpret_cast<uint32_t*>(smem + OFF_PM + b * ROWB + k * 2) = mp;
            }
        }
    }

    float d[2][4][4];
    #pragma unroll
    for (int i = 0; i < 2; i++)
        #pragma unroll
        for (int j = 0; j < 4; j++)
            #pragma unroll
            for (int r = 0; r < 4; r++) d[i][j][r] = 0.0f;

    const int wbase = wid * 32;                 // warp's p-range
    const int bq = lane >> 2;                   // B frag: n index
    const int kq = (lane & 3) * 2;              // B frag: k pair base
    const int lm_m = lane >> 3, lm_r = lane & 7;

    // ---- mainloop over 8 k-stages ----
    #pragma unroll 1
    for (int s = 0; s < NSTG; s++) {
        mbar_wait((s & 1) ? mb1 : mb0, (s >> 1) & 1);

        const float* wbuf = reinterpret_cast<const float*>(smem + OFF_W0 + (s & 1) * W_STAGE_BYTES);
        char* A = smem + OFF_A + (s & 1) * (2 * ATILE);      // hi at A, mid at A+ATILE

        // convert: warp handles rows {wid, wid+8, wid+16, wid+24} of this stage
        #pragma unroll
        for (int j = 0; j < 4; j++) {
            const int r = wid + j * 8;
            const float4 va = *reinterpret_cast<const float4*>(wbuf + r * NN + lane * 4);
            const float4 vb = *reinterpret_cast<const float4*>(wbuf + r * NN + 128 + lane * 4);
            const uint32_t ha0 = cvt2(va.x, va.y), ha1 = cvt2(va.z, va.w);
            const uint32_t hb0 = cvt2(vb.x, vb.y), hb1 = cvt2(vb.z, vb.w);
            const uint32_t ma0 = cvt2(va.x - lo_f(ha0), va.y - hi_f(ha0));
            const uint32_t ma1 = cvt2(va.z - lo_f(ha1), va.w - hi_f(ha1));
            const uint32_t mb_0 = cvt2(vb.x - lo_f(hb0), vb.y - hi_f(hb0));
            const uint32_t mb_1 = cvt2(vb.z - lo_f(hb1), vb.w - hi_f(hb1));
            *reinterpret_cast<uint2*>(A + r * ROWB + lane * 8)               = make_uint2(ha0, ha1);
            *reinterpret_cast<uint2*>(A + r * ROWB + 256 + lane * 8)         = make_uint2(hb0, hb1);
            *reinterpret_cast<uint2*>(A + ATILE + r * ROWB + lane * 8)       = make_uint2(ma0, ma1);
            *reinterpret_cast<uint2*>(A + ATILE + r * ROWB + 256 + lane * 8) = make_uint2(mb_0, mb_1);
        }
        __syncthreads();

        if (tid == 0 && s + 2 < NSTG) {
            uint32_t mb = (s & 1) ? mb1 : mb0;
            mbar_expect_tx(mb, W_STAGE_BYTES);
            bulk_g2s(sbase + OFF_W0 + (s & 1) * W_STAGE_BYTES,
                     wl + (s + 2) * (KSTAGE * NN), W_STAGE_BYTES, mb);
        }

        const uint32_t Asm = sbase + OFF_A + (s & 1) * (2 * ATILE);
        #pragma unroll
        for (int ks = 0; ks < 2; ks++) {
            const int k0 = ks * 16;                      // within stage
            const int kg = s * KSTAGE + k0;              // global k
            // B fragments (shared across p-tiles)
            uint32_t bh[4][2], bm[4][2];
            #pragma unroll
            for (int nt = 0; nt < 4; nt++) {
                const uint32_t off = (uint32_t)((nt * 8 + bq) * ROWB + (kg + kq) * 2);
                bh[nt][0] = *reinterpret_cast<uint32_t*>(smem + OFF_PH + off);
                bh[nt][1] = *reinterpret_cast<uint32_t*>(smem + OFF_PH + off + 16);
                bm[nt][0] = *reinterpret_cast<uint32_t*>(smem + OFF_PM + off);
                bm[nt][1] = *reinterpret_cast<uint32_t*>(smem + OFF_PM + off + 16);
            }
            #pragma unroll
            for (int pt = 0; pt < 2; pt++) {
                const uint32_t lmoff =
                    (uint32_t)((k0 + lm_r + (lm_m >> 1) * 8) * ROWB +
                               (wbase + pt * 16 + (lm_m & 1) * 8) * 2);
                uint32_t ah[4], am[4];
                ldsm4t(ah[0], ah[1], ah[2], ah[3], Asm + lmoff);
                ldsm4t(am[0], am[1], am[2], am[3], Asm + ATILE + lmoff);
                #pragma unroll
                for (int nt = 0; nt < 4; nt++) {
                    mma_bf16(d[pt][nt], ah, bh[nt]);
                    mma_bf16(d[pt][nt], ah, bm[nt]);
                    mma_bf16(d[pt][nt], am, bh[nt]);
                }
            }
        }
    }

    // ---- epilogue: bias + scatter ----
    #pragma unroll
    for (int pt = 0; pt < 2; pt++) {
        const int p0 = wbase + pt * 16 + (lane >> 2);
        const int p1 = p0 + 8;
        const float bv0 = bias[p0 * LL + l];
        const float bv1 = bias[p1 * LL + l];
        const int c0 = p0 >> 2, kh0 = (p0 >> 1) & 1, kw0 = p0 & 1;
        const int c1 = p1 >> 2, kh1 = (p1 >> 1) & 1, kw1 = p1 & 1;
        #pragma unroll
        for (int nt = 0; nt < 4; nt++) {
            const int b = nt * 8 + 2 * (lane & 3);
            const size_t o0 = (size_t)(((b * CC + c0) * HH + 2 * ph + kh0) * HH + 2 * pw + kw0);
            const size_t o1 = (size_t)(((b * CC + c1) * HH + 2 * ph + kh1) * HH + 2 * pw + kw1);
            const size_t bs = (size_t)CC * HH * HH;      // stride between b and b+1
            out[o0]      = d[pt][nt][0] + bv0;
            out[o0 + bs] = d[pt][nt][1] + bv0;
            out[o1]      = d[pt][nt][2] + bv1;
            out[o1 + bs] = d[pt][nt][3] + bv1;
        }
    }
}

extern "C" void kernel_launch(void* const* d_in, const int* in_sizes, int n_in,
                              void* d_out, int out_size)
{
    const float* x    = (const float*)d_in[0];
    const float* w    = (const float*)d_in[1];
    const float* bias = (const float*)d_in[2];
    float* out        = (float*)d_out;

    cudaFuncSetAttribute(pointconv_mma,
                         cudaFuncAttributeMaxDynamicSharedMemorySize, SMEM_TOTAL);
    pointconv_mma<<<LL, 256, SMEM_TOTAL>>>(x, w, bias, out);
}

// round 9
// speedup vs baseline: 1.9240x; 1.0322x over previous
#include <cuda_runtime.h>
#include <cstdint>

// PointConv: B=32, C=64, H=W=64, KH=KW=2 -> L=1024, n=256.
// Per l: D[p, b] = sum_k W[l][k][p] * patch[b][k] + bias[p, l]
// fp32 via 3-term bf16 split on mma.sync.m16n8k16. 2 CTAs/SM (112KB smem each).

#define HH 64
#define CC 64
#define NN 256
#define LL 1024

#define KSTAGE 16
#define NSTG   16
#define W_STAGE_BYTES (KSTAGE * NN * 4)       // 16384
#define NWBUF  3

#define AROW  512                              // 256 p x bf16, XOR-swizzled
#define ATILE (KSTAGE * AROW)                  // 8192 (one of hi/mid)
#define ABUF  (2 * ATILE)                      // 16384 (hi + mid)

#define OFF_W0   0                             // 3 x 16384 = 49152
#define OFF_A    49152                         // 2 x 16384 = 32768
#define OFF_PH   81920                         // 32 x 512 = 16384
#define OFF_PM   98304                         // 16384
#define OFF_CTRL 114688
#define SMEM_TOTAL 114752

typedef unsigned long long u64;

__device__ __forceinline__ uint32_t swz(uint32_t row, uint32_t cb) {
    return row * AROW + (cb ^ ((row & 7) << 4));
}
__device__ __forceinline__ uint32_t cvt2(float lo, float hi) {  // pack {lo=low16, hi=high16}
    uint32_t r;
    asm("cvt.rn.bf16x2.f32 %0, %1, %2;" : "=r"(r) : "f"(hi), "f"(lo));
    return r;
}
__device__ __forceinline__ float lo_f(uint32_t p) { return __uint_as_float(p << 16); }
__device__ __forceinline__ float hi_f(uint32_t p) { return __uint_as_float(p & 0xffff0000u); }

__device__ __forceinline__ void mbar_init(uint32_t mbar, uint32_t count) {
    asm volatile("mbarrier.init.shared::cta.b64 [%0], %1;" :: "r"(mbar), "r"(count) : "memory");
}
__device__ __forceinline__ void mbar_expect_tx(uint32_t mbar, uint32_t bytes) {
    asm volatile("mbarrier.arrive.expect_tx.shared::cta.b64 _, [%0], %1;"
                 :: "r"(mbar), "r"(bytes) : "memory");
}
__device__ __forceinline__ void bulk_g2s(uint32_t dst, const void* src, uint32_t bytes, uint32_t mbar) {
    asm volatile("cp.async.bulk.shared::cta.global.mbarrier::complete_tx::bytes [%0], [%1], %2, [%3];"
                 :: "r"(dst), "l"(src), "r"(bytes), "r"(mbar) : "memory");
}
__device__ __forceinline__ void mbar_wait(uint32_t mbar, uint32_t parity) {
    asm volatile(
        "{\n\t.reg .pred P1;\n\t"
        "WAIT_LOOP_%=:\n\t"
        "mbarrier.try_wait.parity.shared::cta.b64 P1, [%0], %1, 0x989680;\n\t"
        "@P1 bra.uni WAIT_DONE_%=;\n\t"
        "bra.uni WAIT_LOOP_%=;\n\t"
        "WAIT_DONE_%=:\n\t}"
        :: "r"(mbar), "r"(parity) : "memory");
}
__device__ __forceinline__ void ldsm4t(uint32_t& r0, uint32_t& r1, uint32_t& r2, uint32_t& r3,
                                       uint32_t addr) {
    asm volatile("ldmatrix.sync.aligned.m8n8.x4.trans.shared.b16 {%0,%1,%2,%3}, [%4];"
                 : "=r"(r0), "=r"(r1), "=r"(r2), "=r"(r3) : "r"(addr));
}
__device__ __forceinline__ void mma_bf16(float* d, const uint32_t* a, const uint32_t* b) {
    asm volatile(
        "mma.sync.aligned.m16n8k16.row.col.f32.bf16.bf16.f32 "
        "{%0,%1,%2,%3}, {%4,%5,%6,%7}, {%8,%9}, {%0,%1,%2,%3};"
        : "+f"(d[0]), "+f"(d[1]), "+f"(d[2]), "+f"(d[3])
        : "r"(a[0]), "r"(a[1]), "r"(a[2]), "r"(a[3]), "r"(b[0]), "r"(b[1]));
}

__global__ void __launch_bounds__(256, 2)
pointconv_mma(const float* __restrict__ x,
              const float* __restrict__ w,
              const float* __restrict__ bias,
              float* __restrict__ out)
{
    extern __shared__ char smem[];
    const uint32_t sbase = (uint32_t)__cvta_generic_to_shared(smem);
    const int tid  = threadIdx.x;
    const int wid  = tid >> 5;
    const int lane = tid & 31;
    const int l  = blockIdx.x;
    const int ph = l >> 5, pw = l & 31;
    const float* __restrict__ wl = w + (size_t)l * (NN * NN);

    // ---- mbarriers + prefetch first 3 W stages ----
    if (tid == 0) {
        #pragma unroll
        for (int i = 0; i < NWBUF; i++) mbar_init(sbase + OFF_CTRL + i * 8, 1);
        asm volatile("fence.proxy.async.shared::cta;" ::: "memory");
        #pragma unroll
        for (int s = 0; s < NWBUF; s++) {
            uint32_t mb = sbase + OFF_CTRL + s * 8;
            mbar_expect_tx(mb, W_STAGE_BYTES);
            bulk_g2s(sbase + OFF_W0 + s * W_STAGE_BYTES, wl + s * (KSTAGE * NN),
                     W_STAGE_BYTES, mb);
        }
    }

    // ---- patch gather + bf16 hi/mid split -> [b][k] swizzled ----
    {
        const int b  = tid & 31;
        const int cg = tid >> 5;
        #pragma unroll
        for (int ci = 0; ci < 8; ci++) {
            const int c = cg * 8 + ci;
            #pragma unroll
            for (int kh = 0; kh < 2; kh++) {
                const float2 v = *reinterpret_cast<const float2*>(
                    x + (size_t)(((b * CC + c) * HH + 2 * ph + kh) * HH + 2 * pw));
                const int k = c * 4 + kh * 2;
                const uint32_t hp = cvt2(v.x, v.y);
                const uint32_t mp = cvt2(v.x - lo_f(hp), v.y - hi_f(hp));
                const uint32_t a = swz((uint32_t)b, (uint32_t)(k * 2));
                *reinterpret_cast<uint32_t*>(smem + OFF_PH + a) = hp;
                *reinterpret_cast<uint32_t*>(smem + OFF_PM + a) = mp;
            }
        }
    }

    float d[2][4][4];
    #pragma unroll
    for (int i = 0; i < 2; i++)
        #pragma unroll
        for (int j = 0; j < 4; j++)
            #pragma unroll
            for (int r = 0; r < 4; r++) d[i][j][r] = 0.0f;

    const int wbase = wid * 32;
    const int bq = lane >> 2;
    const int kq = (lane & 3) * 2;
    const int lm_m = lane >> 3, lm_r = lane & 7;

    // ---- mainloop over 16 k-stages, 3-deep TMA ring, double-buffered A ----
    #pragma unroll 1
    for (int s = 0; s < NSTG; s++) {
        const int wb = s % NWBUF;
        mbar_wait(sbase + OFF_CTRL + wb * 8, (s / NWBUF) & 1);

        const float* wbuf = reinterpret_cast<const float*>(smem + OFF_W0 + wb * W_STAGE_BYTES);
        char* A = smem + OFF_A + (s & 1) * ABUF;            // hi at A, mid at A+ATILE

        // convert: warp handles rows {wid, wid+8}
        #pragma unroll
        for (int j = 0; j < 2; j++) {
            const int r = wid + j * 8;
            const float4 va = *reinterpret_cast<const float4*>(wbuf + r * NN + lane * 4);
            const float4 vb = *reinterpret_cast<const float4*>(wbuf + r * NN + 128 + lane * 4);
            const uint32_t ha0 = cvt2(va.x, va.y), ha1 = cvt2(va.z, va.w);
            const uint32_t hb0 = cvt2(vb.x, vb.y), hb1 = cvt2(vb.z, vb.w);
            const uint32_t ma0 = cvt2(va.x - lo_f(ha0), va.y - hi_f(ha0));
            const uint32_t ma1 = cvt2(va.z - lo_f(ha1), va.w - hi_f(ha1));
            const uint32_t mb0 = cvt2(vb.x - lo_f(hb0), vb.y - hi_f(hb0));
            const uint32_t mb1 = cvt2(vb.z - lo_f(hb1), vb.w - hi_f(hb1));
            const uint32_t a0 = swz((uint32_t)r, (uint32_t)(lane * 8));
            const uint32_t a1 = swz((uint32_t)r, (uint32_t)(256 + lane * 8));
            *reinterpret_cast<uint2*>(A + a0)         = make_uint2(ha0, ha1);
            *reinterpret_cast<uint2*>(A + a1)         = make_uint2(hb0, hb1);
            *reinterpret_cast<uint2*>(A + ATILE + a0) = make_uint2(ma0, ma1);
            *reinterpret_cast<uint2*>(A + ATILE + a1) = make_uint2(mb0, mb1);
        }
        __syncthreads();

        if (tid == 0 && s + NWBUF < NSTG) {
            uint32_t mb = sbase + OFF_CTRL + wb * 8;
            mbar_expect_tx(mb, W_STAGE_BYTES);
            bulk_g2s(sbase + OFF_W0 + wb * W_STAGE_BYTES,
                     wl + (s + NWBUF) * (KSTAGE * NN), W_STAGE_BYTES, mb);
        }

        // B fragments for this stage's k16 chunk
        const int kg = s * KSTAGE;
        uint32_t bh[4][2], bm[4][2];
        #pragma unroll
        for (int nt = 0; nt < 4; nt++) {
            const uint32_t row = (uint32_t)(nt * 8 + bq);
            const uint32_t o0 = swz(row, (uint32_t)((kg + kq) * 2));
            const uint32_t o1 = swz(row, (uint32_t)((kg + kq) * 2 + 16));
            bh[nt][0] = *reinterpret_cast<uint32_t*>(smem + OFF_PH + o0);
            bh[nt][1] = *reinterpret_cast<uint32_t*>(smem + OFF_PH + o1);
            bm[nt][0] = *reinterpret_cast<uint32_t*>(smem + OFF_PM + o0);
            bm[nt][1] = *reinterpret_cast<uint32_t*>(smem + OFF_PM + o1);
        }

        const uint32_t Asm = sbase + OFF_A + (s & 1) * ABUF;
        #pragma unroll
        for (int pt = 0; pt < 2; pt++) {
            const uint32_t row = (uint32_t)(lm_r + (lm_m >> 1) * 8);
            const uint32_t cb  = (uint32_t)((wbase + pt * 16 + (lm_m & 1) * 8) * 2);
            const uint32_t lmoff = swz(row, cb);
            uint32_t ah[4], am[4];
            ldsm4t(ah[0], ah[1], ah[2], ah[3], Asm + lmoff);
            ldsm4t(am[0], am[1], am[2], am[3], Asm + ATILE + lmoff);
            #pragma unroll
            for (int nt = 0; nt < 4; nt++) {
                mma_bf16(d[pt][nt], ah, bh[nt]);
                mma_bf16(d[pt][nt], ah, bm[nt]);
                mma_bf16(d[pt][nt], am, bh[nt]);
            }
        }
    }

    // ---- epilogue: bias + scatter ----
    #pragma unroll
    for (int pt = 0; pt < 2; pt++) {
        const int p0 = wbase + pt * 16 + (lane >> 2);
        const int p1 = p0 + 8;
        const float bv0 = bias[p0 * LL + l];
        const float bv1 = bias[p1 * LL + l];
        const int c0 = p0 >> 2, kh0 = (p0 >> 1) & 1, kw0 = p0 & 1;
        const int c1 = p1 >> 2, kh1 = (p1 >> 1) & 1, kw1 = p1 & 1;
        #pragma unroll
        for (int nt = 0; nt < 4; nt++) {
            const int b = nt * 8 + 2 * (lane & 3);
            const size_t o0 = (size_t)(((b * CC + c0) * HH + 2 * ph + kh0) * HH + 2 * pw + kw0);
            const size_t o1 = (size_t)(((b * CC + c1) * HH + 2 * ph + kh1) * HH + 2 * pw + kw1);
            const size_t bs = (size_t)CC * HH * HH;
            out[o0]      = d[pt][nt][0] + bv0;
            out[o0 + bs] = d[pt][nt][1] + bv0;
            out[o1]      = d[pt][nt][2] + bv1;
            out[o1 + bs] = d[pt][nt][3] + bv1;
        }
    }
}

extern "C" void kernel_launch(void* const* d_in, const int* in_sizes, int n_in,
                              void* d_out, int out_size)
{
    const float* x    = (const float*)d_in[0];
    const float* w    = (const float*)d_in[1];
    const float* bias = (const float*)d_in[2];
    float* out        = (float*)d_out;

    cudaFuncSetAttribute(pointconv_mma,
                         cudaFuncAttributeMaxDynamicSharedMemorySize, SMEM_TOTAL);
    pointconv_mma<<<LL, 256, SMEM_TOTAL>>>(x, w, bias, out);
}